// round 5
// baseline (speedup 1.0000x reference)
#include <cuda_runtime.h>
#include <cuda_bf16.h>

#define NN   100000
#define EE   1600000
#define DIMM 128
#define HH   5
#define CC   10
#define HC   50
#define GG   256
#define NEG_SLOPE 0.2f

// ---------------- static scratch (no allocation allowed) ----------------
__device__ float g_xw  [NN * HC];   // x @ W             20 MB
__device__ float g_asrc[NN * HH];   // per-node src attn  2 MB
__device__ float g_adst[NN * HH];   // per-node dst attn  2 MB
__device__ float g_gout[NN * HC];   // elu(node output)  20 MB
__device__ int   g_deg   [NN];
__device__ int   g_off   [NN];
__device__ int   g_cursor[NN];
__device__ int   g_csr   [EE + NN]; // src ids grouped by dst (incl. self-loops)
__device__ int   g_cnt   [GG];
__device__ int   g_goff  [GG + 1];
__device__ int   g_is64;            // 1 if index buffers are int64, 0 if int32

// ---------------- dtype probe: int64 vs int32 index buffers ----------------
// If int64 (values < 2^31, nonneg), every odd int32 word is 0. For real int32
// node ids (random in [0,1e5)) the chance 64 samples are all zero is ~0.
__global__ void detect_kernel(const int* __restrict__ ei32) {
    if (threadIdx.x != 0 || blockIdx.x != 0) return;
    int ok = 1;
    #pragma unroll 1
    for (int s = 1; s < 129; s += 2)
        if (ei32[s] != 0) { ok = 0; break; }
    g_is64 = ok;
}

__device__ __forceinline__ int load_idx(const void* p, long long i, int is64) {
    int v = is64 ? (int)((const long long*)p)[i] : ((const int*)p)[i];
    return min(max(v, 0), NN - 1);    // defensive clamp (dead when dtype right)
}

// ---------------- init: deg=1 (self loop), cnt=0 ----------------
__global__ void init_kernel() {
    int i = blockIdx.x * blockDim.x + threadIdx.x;
    if (i < NN) g_deg[i] = 1;
    if (i < GG) g_cnt[i] = 0;
}

// ---------------- histogram of edge dst ----------------
__global__ void hist_kernel(const void* __restrict__ ei) {
    int e = blockIdx.x * blockDim.x + threadIdx.x;
    if (e >= EE) return;
    int d = load_idx(ei, (long long)EE + e, g_is64);
    atomicAdd(&g_deg[d], 1);
}

// ---------------- histogram of batch (graph sizes) ----------------
__global__ void bhist_kernel(const void* __restrict__ batch) {
    int i = blockIdx.x * blockDim.x + threadIdx.x;
    if (i >= NN) return;
    int b = load_idx(batch, i, g_is64);
    atomicAdd(&g_cnt[min(b, GG - 1)], 1);
}

// ---------------- exclusive scan of deg -> off, cursor ----------------
__global__ void scan_deg_kernel() {
    __shared__ int part[1024];
    const int CH = (NN + 1023) / 1024;   // 98
    int t = threadIdx.x;
    int s = t * CH;
    int e = min(s + CH, NN);
    int sum = 0;
    for (int i = s; i < e; i++) sum += g_deg[i];
    part[t] = sum;
    __syncthreads();
    int acc = sum;
    for (int d = 1; d < 1024; d <<= 1) {
        int add = (t >= d) ? part[t - d] : 0;
        __syncthreads();
        acc += add;
        part[t] = acc;
        __syncthreads();
    }
    int run = acc - sum;                 // exclusive prefix
    for (int i = s; i < e; i++) {
        g_off[i] = run;
        g_cursor[i] = run;
        run += g_deg[i];
    }
}

// ---------------- scan of graph counts -> graph offsets ----------------
__global__ void scan_cnt_kernel() {
    __shared__ int part[GG];
    int t = threadIdx.x;
    int v = g_cnt[t];
    part[t] = v;
    __syncthreads();
    int acc = v;
    for (int d = 1; d < GG; d <<= 1) {
        int add = (t >= d) ? part[t - d] : 0;
        __syncthreads();
        acc += add;
        part[t] = acc;
        __syncthreads();
    }
    g_goff[t + 1] = acc;
    if (t == 0) g_goff[0] = 0;
}

// ---------------- scatter edges (and self loops) into CSR ----------------
__global__ void scatter_kernel(const void* __restrict__ ei) {
    int idx = blockIdx.x * blockDim.x + threadIdx.x;
    if (idx >= EE + NN) return;
    int j, d;
    if (idx < EE) {
        int is64 = g_is64;
        j = load_idx(ei, idx, is64);
        d = load_idx(ei, (long long)EE + idx, is64);
    } else {
        j = d = idx - EE;
    }
    int pos = atomicAdd(&g_cursor[d], 1);
    g_csr[pos] = j;
}

// ---------------- GEMM: xw = x @ W ----------------
// 64-node x 64-col (50 real) tile, K=128 in two 64-chunks, static smem 33.8 KB.
// W staged TRANSPOSED so both operands stream as conflict-free LDS.64.
#define KC 64
#define XS_STRIDE 66   // even -> aligned float2 at even k
__global__ void __launch_bounds__(256, 4) gemm_kernel(const float* __restrict__ x,
                                                      const float* __restrict__ W) {
    __shared__ float xs [64][XS_STRIDE];   // nodes x k-chunk
    __shared__ float wst[64][XS_STRIDE];   // cols  x k-chunk (transposed W)
    int t = threadIdx.x;
    int n0 = blockIdx.x * 64;
    int tx = t & 15, ty = t >> 4;

    float acc[4][4] = {};

    for (int kc = 0; kc < 2; kc++) {
        int k0 = kc * KC;
        for (int idx = t; idx < 64 * 16; idx += 256) {
            int r = idx >> 4, q = idx & 15;
            int gn = n0 + r;
            float4 v = (gn < NN)
                ? *reinterpret_cast<const float4*>(&x[gn * DIMM + k0 + q * 4])
                : make_float4(0.f, 0.f, 0.f, 0.f);
            xs[r][q * 4 + 0] = v.x; xs[r][q * 4 + 1] = v.y;
            xs[r][q * 4 + 2] = v.z; xs[r][q * 4 + 3] = v.w;
        }
        for (int idx = t; idx < 64 * 64; idx += 256) {
            int k = idx >> 6, c = idx & 63;
            wst[c][k] = (c < HC) ? W[(k0 + k) * HC + c] : 0.f;
        }
        __syncthreads();

        #pragma unroll 4
        for (int k = 0; k < KC; k += 2) {
            float2 xv[4], wv[4];
            #pragma unroll
            for (int m = 0; m < 4; m++)
                xv[m] = *reinterpret_cast<const float2*>(&xs[ty + 16 * m][k]);
            #pragma unroll
            for (int n = 0; n < 4; n++)
                wv[n] = *reinterpret_cast<const float2*>(&wst[tx + 16 * n][k]);
            #pragma unroll
            for (int m = 0; m < 4; m++)
                #pragma unroll
                for (int n = 0; n < 4; n++) {
                    acc[m][n] += xv[m].x * wv[n].x;
                    acc[m][n] += xv[m].y * wv[n].y;
                }
        }
        __syncthreads();
    }

    #pragma unroll
    for (int m = 0; m < 4; m++) {
        int gn = n0 + ty + 16 * m;
        if (gn >= NN) continue;
        #pragma unroll
        for (int n = 0; n < 4; n++) {
            int c = tx + 16 * n;
            if (c < HC) g_xw[gn * HC + c] = acc[m][n];
        }
    }
}

// ---------------- per-node attention scalars ----------------
__global__ void att_kernel(const float* __restrict__ att_src,
                           const float* __restrict__ att_dst) {
    int idx = blockIdx.x * blockDim.x + threadIdx.x;   // N*H
    if (idx >= NN * HH) return;
    int n = idx / HH, h = idx % HH;
    const float* xr = &g_xw[n * HC + h * CC];
    float s = 0.f, d = 0.f;
    #pragma unroll
    for (int c = 0; c < CC; c++) {
        float v = xr[c];
        s += v * att_src[h * CC + c];
        d += v * att_dst[h * CC + c];
    }
    g_asrc[idx] = s;
    g_adst[idx] = d;
}

// ---------------- main aggregation: one warp per dst node ----------------
// single pass: acc[h,c] += exp(leaky(a_src+a_dst)) * xw[src], denom[h] += exp
// (softmax max-subtraction dropped: logits are O(1); softmax is shift-invariant)
__global__ void aggregate_kernel(const float* __restrict__ bias) {
    int gw   = (blockIdx.x * blockDim.x + threadIdx.x) >> 5;
    int lane = threadIdx.x & 31;
    if (gw >= NN) return;

    int base = g_off[gw];
    int deg  = g_deg[gw];
    float adst = (lane < HH) ? g_adst[gw * HH + lane] : 0.f;

    float2 acc = make_float2(0.f, 0.f);
    float denom = 0.f;
    int h = lane / 5;            // head owning this lane's channel pair (lanes<25)

    for (int c0 = 0; c0 < deg; c0 += 32) {
        int jv = (c0 + lane < deg) ? g_csr[base + c0 + lane] : 0;
        int m = min(32, deg - c0);
        #pragma unroll 4
        for (int e = 0; e < m; e++) {
            int j = __shfl_sync(0xffffffffu, jv, e);
            float ex = 0.f;
            if (lane < HH) {
                float tt = __ldg(&g_asrc[j * HH + lane]) + adst;
                tt = (tt > 0.f) ? tt : NEG_SLOPE * tt;
                ex = __expf(tt);
                denom += ex;
            }
            float exh = __shfl_sync(0xffffffffu, ex, h);
            if (lane < 25) {
                float2 v = *reinterpret_cast<const float2*>(&g_xw[j * HC + lane * 2]);
                acc.x += exh * v.x;
                acc.y += exh * v.y;
            }
        }
    }

    float dh = __shfl_sync(0xffffffffu, denom, h);
    if (lane < 25) {
        int c = lane * 2;
        float ox = acc.x / dh + bias[c];
        float oy = acc.y / dh + bias[c + 1];
        ox = (ox > 0.f) ? ox : expm1f(ox);       // ELU fused here
        oy = (oy > 0.f) ? oy : expm1f(oy);
        *reinterpret_cast<float2*>(&g_gout[gw * HC + c]) = make_float2(ox, oy);
    }
}

// ---------------- pool (mean per graph) + linear + sigmoid ----------------
__global__ void pool_kernel(const float* __restrict__ lin_w,
                            const float* __restrict__ lin_b,
                            float* __restrict__ out) {
    __shared__ float red[5][HC];
    __shared__ float hsh[HC];
    int t = threadIdx.x, g = blockIdx.x;
    int start = g_goff[g], end = g_goff[g + 1];
    int cnt = end - start;

    if (t < 250) {
        int nd = t / HC, c = t % HC;
        float p = 0.f;
        for (int r = start + nd; r < end; r += 5) p += g_gout[r * HC + c];
        red[nd][c] = p;
    }
    __syncthreads();
    if (t < HC) {
        float s = red[0][t] + red[1][t] + red[2][t] + red[3][t] + red[4][t];
        float hv = s / fmaxf((float)cnt, 1.f);
        out[g * HC + t] = hv;
        hsh[t] = hv * lin_w[t];
    }
    __syncthreads();
    if (t == 0) {
        float s = lin_b[0];
        #pragma unroll
        for (int c = 0; c < HC; c++) s += hsh[c];
        out[GG * HC + g] = 1.f / (1.f + __expf(-s));
    }
}

// ---------------- launch ----------------
extern "C" void kernel_launch(void* const* d_in, const int* in_sizes, int n_in,
                              void* d_out, int out_size) {
    const float* x       = (const float*)d_in[0];
    const float* W       = (const float*)d_in[1];
    const float* att_src = (const float*)d_in[2];
    const float* att_dst = (const float*)d_in[3];
    const float* bias    = (const float*)d_in[4];
    const float* lin_w   = (const float*)d_in[5];
    const float* lin_b   = (const float*)d_in[6];
    const void*  ei      = d_in[7];
    const void*  batch   = d_in[8];
    float*       out     = (float*)d_out;

    detect_kernel  <<<1, 32>>>((const int*)ei);
    init_kernel    <<<(NN + 255) / 256, 256>>>();
    hist_kernel    <<<(EE + 255) / 256, 256>>>(ei);
    bhist_kernel   <<<(NN + 255) / 256, 256>>>(batch);
    scan_deg_kernel<<<1, 1024>>>();
    scan_cnt_kernel<<<1, GG>>>();
    scatter_kernel <<<(EE + NN + 255) / 256, 256>>>(ei);

    gemm_kernel    <<<(NN + 63) / 64, 256>>>(x, W);
    att_kernel     <<<(NN * HH + 255) / 256, 256>>>(att_src, att_dst);

    aggregate_kernel<<<NN / 8, 256>>>(bias);   // 1 warp per node, 8 warps/block

    pool_kernel    <<<GG, 256>>>(lin_w, lin_b, out);
}

// round 7
// speedup vs baseline: 2.1462x; 2.1462x over previous
#include <cuda_runtime.h>
#include <cuda_bf16.h>

#define NN   100000
#define EE   1600000
#define DIMM 128
#define HH   5
#define CC   10
#define HC   50
#define GG   256
#define NEG_SLOPE 0.2f
#define NB   391            // ceil(NN/256)

// ---------------- static scratch (no allocation allowed) ----------------
__device__ float g_xw  [NN * HC];   // x @ W             20 MB
__device__ float g_asrc[NN * HH];   // per-node src attn  2 MB
__device__ float g_adst[NN * HH];   // per-node dst attn  2 MB
__device__ float g_gout[NN * HC];   // elu(node output)  20 MB
__device__ int   g_deg   [NN];
__device__ int   g_off   [NN];
__device__ int   g_cursor[NN];
__device__ int   g_csr   [EE + NN]; // src ids grouped by dst (incl. self-loops)
__device__ int   g_part  [512];     // scan partials
__device__ int   g_goff  [GG + 1];
__device__ int   g_is64;            // 1 if index buffers are int64, 0 if int32

// ---------------- dtype probe (warp-parallel) ----------------
// int64 values < 2^31 -> every odd int32 word is 0. Random int32 node ids
// would hit nonzero hi-words immediately.
__global__ void detect_kernel(const int* __restrict__ ei32) {
    int t = threadIdx.x;                    // 64 threads
    int nz = (ei32[2 * t + 1] != 0) ? 1 : 0;
    unsigned b0 = __ballot_sync(0xffffffffu, nz && t < 32);
    __shared__ int hi;
    if (t == 32) hi = 0;
    __syncthreads();
    if (t >= 32 && nz) atomicOr(&hi, 1);
    __syncthreads();
    if (t == 0) g_is64 = (b0 == 0u && hi == 0) ? 1 : 0;
}

__device__ __forceinline__ int load_idx(const void* p, long long i, int is64) {
    int v = is64 ? (int)((const long long*)p)[i] : ((const int*)p)[i];
    return min(max(v, 0), NN - 1);    // defensive clamp (dead when dtype right)
}

// ---------------- init: deg=1 (self loop) ----------------
__global__ void init_kernel() {
    int i = blockIdx.x * blockDim.x + threadIdx.x;
    if (i < NN) g_deg[i] = 1;
}

// ---------------- histogram of edge dst (random addrs -> fine) -----------
__global__ void hist_kernel(const void* __restrict__ ei) {
    int e = blockIdx.x * blockDim.x + threadIdx.x;
    if (e >= EE) return;
    int d = load_idx(ei, (long long)EE + e, g_is64);
    atomicAdd(&g_deg[d], 1);
}

// ---------------- graph offsets from SORTED batch (no atomics) -----------
__global__ void goff_kernel(const void* __restrict__ batch) {
    int i = blockIdx.x * blockDim.x + threadIdx.x;
    if (i >= NN) return;
    int is64 = g_is64;
    int b = min(load_idx(batch, i, is64), GG - 1);
    int prev = (i == 0) ? -1 : min(load_idx(batch, i - 1, is64), GG - 1);
    for (int g = prev + 1; g <= b; g++) g_goff[g] = i;     // starts
    if (i == NN - 1)
        for (int g = b + 1; g <= GG; g++) g_goff[g] = NN;  // tail (incl. empty)
}

// ---------------- hierarchical exclusive scan of deg ----------------
__global__ void scan1_kernel() {          // block sums
    __shared__ int ws[8];
    int i = blockIdx.x * 256 + threadIdx.x;
    int lane = threadIdx.x & 31, w = threadIdx.x >> 5;
    int v = (i < NN) ? g_deg[i] : 0;
    int s = v;
    #pragma unroll
    for (int o = 16; o; o >>= 1) s += __shfl_xor_sync(0xffffffffu, s, o);
    if (lane == 0) ws[w] = s;
    __syncthreads();
    if (threadIdx.x == 0) {
        int tot = 0;
        #pragma unroll
        for (int k = 0; k < 8; k++) tot += ws[k];
        g_part[blockIdx.x] = tot;
    }
}

__global__ void scan2_kernel() {          // scan 391 partials (1 block, 512 thr)
    __shared__ int sm[512];
    int t = threadIdx.x;
    int v = (t < NB) ? g_part[t] : 0;
    sm[t] = v;
    __syncthreads();
    int acc = v;
    for (int d = 1; d < 512; d <<= 1) {
        int a = (t >= d) ? sm[t - d] : 0;
        __syncthreads();
        acc += a;
        sm[t] = acc;
        __syncthreads();
    }
    if (t < NB) g_part[t] = acc - v;      // exclusive block base
}

__global__ void scan3_kernel() {          // local exclusive scan + base
    __shared__ int wsum[8];
    int b = blockIdx.x, t = threadIdx.x;
    int i = b * 256 + t;
    int lane = t & 31, w = t >> 5;
    int v = (i < NN) ? g_deg[i] : 0;
    int sc = v;
    #pragma unroll
    for (int o = 1; o < 32; o <<= 1) {
        int u = __shfl_up_sync(0xffffffffu, sc, o);
        if (lane >= o) sc += u;
    }
    if (lane == 31) wsum[w] = sc;
    __syncthreads();
    if (t < 8) {
        int x = wsum[t];
        #pragma unroll
        for (int o = 1; o < 8; o <<= 1) {
            int u = __shfl_up_sync(0xffu, x, o);
            if (t >= o) x += u;
        }
        wsum[t] = x;                      // inclusive warp-total scan
    }
    __syncthreads();
    int excl = sc - v + (w > 0 ? wsum[w - 1] : 0) + g_part[b];
    if (i < NN) { g_off[i] = excl; g_cursor[i] = excl; }
}

// ---------------- scatter edges (and self loops) into CSR ----------------
__global__ void scatter_kernel(const void* __restrict__ ei) {
    int idx = blockIdx.x * blockDim.x + threadIdx.x;
    if (idx >= EE + NN) return;
    int j, d;
    if (idx < EE) {
        int is64 = g_is64;
        j = load_idx(ei, idx, is64);
        d = load_idx(ei, (long long)EE + idx, is64);
    } else {
        j = d = idx - EE;
    }
    int pos = atomicAdd(&g_cursor[d], 1);
    g_csr[pos] = j;
}

// ---------------- GEMM: xw = x @ W ----------------
// 64-node x 64-col (50 real) tile, K=128 in two 64-chunks, static smem 33.8 KB.
// W staged TRANSPOSED so both operands stream as conflict-free LDS.64.
#define KC 64
#define XS_STRIDE 66
__global__ void __launch_bounds__(256, 4) gemm_kernel(const float* __restrict__ x,
                                                      const float* __restrict__ W) {
    __shared__ float xs [64][XS_STRIDE];
    __shared__ float wst[64][XS_STRIDE];
    int t = threadIdx.x;
    int n0 = blockIdx.x * 64;
    int tx = t & 15, ty = t >> 4;

    float acc[4][4] = {};

    for (int kc = 0; kc < 2; kc++) {
        int k0 = kc * KC;
        for (int idx = t; idx < 64 * 16; idx += 256) {
            int r = idx >> 4, q = idx & 15;
            int gn = n0 + r;
            float4 v = (gn < NN)
                ? *reinterpret_cast<const float4*>(&x[gn * DIMM + k0 + q * 4])
                : make_float4(0.f, 0.f, 0.f, 0.f);
            xs[r][q * 4 + 0] = v.x; xs[r][q * 4 + 1] = v.y;
            xs[r][q * 4 + 2] = v.z; xs[r][q * 4 + 3] = v.w;
        }
        for (int idx = t; idx < 64 * 64; idx += 256) {
            int k = idx >> 6, c = idx & 63;
            wst[c][k] = (c < HC) ? W[(k0 + k) * HC + c] : 0.f;
        }
        __syncthreads();

        #pragma unroll 4
        for (int k = 0; k < KC; k += 2) {
            float2 xv[4], wv[4];
            #pragma unroll
            for (int m = 0; m < 4; m++)
                xv[m] = *reinterpret_cast<const float2*>(&xs[ty + 16 * m][k]);
            #pragma unroll
            for (int n = 0; n < 4; n++)
                wv[n] = *reinterpret_cast<const float2*>(&wst[tx + 16 * n][k]);
            #pragma unroll
            for (int m = 0; m < 4; m++)
                #pragma unroll
                for (int n = 0; n < 4; n++) {
                    acc[m][n] += xv[m].x * wv[n].x;
                    acc[m][n] += xv[m].y * wv[n].y;
                }
        }
        __syncthreads();
    }

    #pragma unroll
    for (int m = 0; m < 4; m++) {
        int gn = n0 + ty + 16 * m;
        if (gn >= NN) continue;
        #pragma unroll
        for (int n = 0; n < 4; n++) {
            int c = tx + 16 * n;
            if (c < HC) g_xw[gn * HC + c] = acc[m][n];
        }
    }
}

// ---------------- per-node attention scalars ----------------
__global__ void att_kernel(const float* __restrict__ att_src,
                           const float* __restrict__ att_dst) {
    int idx = blockIdx.x * blockDim.x + threadIdx.x;   // N*H
    if (idx >= NN * HH) return;
    int n = idx / HH, h = idx % HH;
    const float* xr = &g_xw[n * HC + h * CC];
    float s = 0.f, d = 0.f;
    #pragma unroll
    for (int c = 0; c < CC; c++) {
        float v = xr[c];
        s += v * att_src[h * CC + c];
        d += v * att_dst[h * CC + c];
    }
    g_asrc[idx] = s;
    g_adst[idx] = d;
}

// ---------------- aggregation: warp/node, 2-phase per 32-edge chunk -------
// Phase A (edge-parallel): lane e computes exp(leaky(asrc[j]+adst)) for its
// edge's 5 heads, stages j + 5 ex to interleaved smem, accumulates denom.
// Phase B (channel-parallel): lanes<25 accumulate xw[j]*ex via broadcast LDS.
// Softmax max-subtraction dropped: logits O(1), softmax shift-invariant.
#define EST 6   // smem record stride: [j, ex0..ex4]
__global__ void __launch_bounds__(256) aggregate_kernel(const float* __restrict__ bias) {
    __shared__ float esh[8][32 * EST];

    int w    = threadIdx.x >> 5;
    int lane = threadIdx.x & 31;
    int gw   = blockIdx.x * 8 + w;

    int base = g_off[gw];
    int deg  = g_deg[gw];

    float ad[HH];
    #pragma unroll
    for (int h = 0; h < HH; h++) ad[h] = g_adst[gw * HH + h];

    int   hsel = lane / 5;                 // head for this lane's channel pair
    float dacc[HH] = {};
    float2 acc = make_float2(0.f, 0.f);

    for (int c0 = 0; c0 < deg; c0 += 32) {
        int m = min(32, deg - c0);
        // ---- phase A ----
        float* rec = &esh[w][lane * EST];
        if (lane < m) {
            int j = g_csr[base + c0 + lane];
            rec[0] = __int_as_float(j);
            const float* ap = &g_asrc[j * HH];
            #pragma unroll
            for (int h = 0; h < HH; h++) {
                float tt = __ldg(&ap[h]) + ad[h];
                tt = (tt > 0.f) ? tt : NEG_SLOPE * tt;
                float e = __expf(tt);
                rec[1 + h] = e;
                dacc[h] += e;
            }
        }
        __syncwarp();
        // ---- phase B ----
        if (lane < 25) {
            #pragma unroll 8
            for (int e = 0; e < m; e++) {
                const float* r = &esh[w][e * EST];
                int   je  = __float_as_int(r[0]);
                float exh = r[1 + hsel];
                float2 v = *reinterpret_cast<const float2*>(&g_xw[je * HC + lane * 2]);
                acc.x += exh * v.x;
                acc.y += exh * v.y;
            }
        }
        __syncwarp();
    }

    // reduce denominators across lanes
    #pragma unroll
    for (int h = 0; h < HH; h++) {
        #pragma unroll
        for (int o = 16; o; o >>= 1)
            dacc[h] += __shfl_xor_sync(0xffffffffu, dacc[h], o);
    }
    float dh = dacc[0];
    #pragma unroll
    for (int h = 1; h < HH; h++) if (hsel == h) dh = dacc[h];

    if (lane < 25) {
        int c = lane * 2;
        float ox = acc.x / dh + bias[c];
        float oy = acc.y / dh + bias[c + 1];
        ox = (ox > 0.f) ? ox : expm1f(ox);       // ELU fused
        oy = (oy > 0.f) ? oy : expm1f(oy);
        *reinterpret_cast<float2*>(&g_gout[gw * HC + c]) = make_float2(ox, oy);
    }
}

// ---------------- pool (mean per graph) + linear + sigmoid ----------------
__global__ void pool_kernel(const float* __restrict__ lin_w,
                            const float* __restrict__ lin_b,
                            float* __restrict__ out) {
    __shared__ float red[5][HC];
    __shared__ float hsh[HC];
    int t = threadIdx.x, g = blockIdx.x;
    int start = g_goff[g], end = g_goff[g + 1];
    int cnt = end - start;

    if (t < 250) {
        int nd = t / HC, c = t % HC;
        float p = 0.f;
        for (int r = start + nd; r < end; r += 5) p += g_gout[r * HC + c];
        red[nd][c] = p;
    }
    __syncthreads();
    if (t < HC) {
        float s = red[0][t] + red[1][t] + red[2][t] + red[3][t] + red[4][t];
        float hv = s / fmaxf((float)cnt, 1.f);
        out[g * HC + t] = hv;
        hsh[t] = hv * lin_w[t];
    }
    __syncthreads();
    if (t == 0) {
        float s = lin_b[0];
        #pragma unroll
        for (int c = 0; c < HC; c++) s += hsh[c];
        out[GG * HC + g] = 1.f / (1.f + __expf(-s));
    }
}

// ---------------- launch ----------------
extern "C" void kernel_launch(void* const* d_in, const int* in_sizes, int n_in,
                              void* d_out, int out_size) {
    const float* x       = (const float*)d_in[0];
    const float* W       = (const float*)d_in[1];
    const float* att_src = (const float*)d_in[2];
    const float* att_dst = (const float*)d_in[3];
    const float* bias    = (const float*)d_in[4];
    const float* lin_w   = (const float*)d_in[5];
    const float* lin_b   = (const float*)d_in[6];
    const void*  ei      = d_in[7];
    const void*  batch   = d_in[8];
    float*       out     = (float*)d_out;

    detect_kernel <<<1, 64>>>((const int*)ei);
    init_kernel   <<<NB, 256>>>();
    hist_kernel   <<<(EE + 255) / 256, 256>>>(ei);
    goff_kernel   <<<NB, 256>>>(batch);
    scan1_kernel  <<<NB, 256>>>();
    scan2_kernel  <<<1, 512>>>();
    scan3_kernel  <<<NB, 256>>>();
    scatter_kernel<<<(EE + NN + 255) / 256, 256>>>(ei);

    gemm_kernel   <<<(NN + 63) / 64, 256>>>(x, W);
    att_kernel    <<<(NN * HH + 255) / 256, 256>>>(att_src, att_dst);

    aggregate_kernel<<<NN / 8, 256>>>(bias);   // 1 warp per node

    pool_kernel   <<<GG, 256>>>(lin_w, lin_b, out);
}

// round 8
// speedup vs baseline: 2.2619x; 1.0539x over previous
#include <cuda_runtime.h>
#include <cuda_bf16.h>

#define NN   100000
#define EE   1600000
#define DIMM 128
#define HH   5
#define CC   10
#define HC   50
#define GG   256
#define NEG_SLOPE 0.2f
#define NB   391            // ceil(NN/256)

// ---------------- static scratch (no allocation allowed) ----------------
__device__ __nv_bfloat16 g_xwh[NN * HC];  // bf16 x@W (messages)   10 MB
__device__ float g_asrc8[NN * 8];   // src attn, padded row of 8   3.2 MB
__device__ float g_adst8[NN * 8];   // dst attn, padded row of 8   3.2 MB
__device__ float g_gout [NN * HC];  // elu(node output)            20 MB
__device__ int   g_deg   [NN];
__device__ int   g_off   [NN];
__device__ int   g_cursor[NN];
__device__ int   g_csr   [EE + NN]; // src ids grouped by dst (incl. self-loops)
__device__ int   g_part  [512];     // scan partials
__device__ int   g_goff  [GG + 1];
__device__ int   g_is64;            // 1 if index buffers are int64, 0 if int32

// ---------------- dtype probe (warp-parallel) ----------------
__global__ void detect_kernel(const int* __restrict__ ei32) {
    int t = threadIdx.x;                    // 64 threads
    int nz = (ei32[2 * t + 1] != 0) ? 1 : 0;
    unsigned b0 = __ballot_sync(0xffffffffu, nz && t < 32);
    __shared__ int hi;
    if (t == 32) hi = 0;
    __syncthreads();
    if (t >= 32 && nz) atomicOr(&hi, 1);
    __syncthreads();
    if (t == 0) g_is64 = (b0 == 0u && hi == 0) ? 1 : 0;
}

__device__ __forceinline__ int load_idx(const void* p, long long i, int is64) {
    int v = is64 ? (int)((const long long*)p)[i] : ((const int*)p)[i];
    return min(max(v, 0), NN - 1);    // defensive clamp (dead when dtype right)
}

// ---------------- init: deg=1 (self loop) ----------------
__global__ void init_kernel() {
    int i = blockIdx.x * blockDim.x + threadIdx.x;
    if (i < NN) g_deg[i] = 1;
}

// ---------------- histogram of edge dst ----------------
__global__ void hist_kernel(const void* __restrict__ ei) {
    int e = blockIdx.x * blockDim.x + threadIdx.x;
    if (e >= EE) return;
    int d = load_idx(ei, (long long)EE + e, g_is64);
    atomicAdd(&g_deg[d], 1);
}

// ---------------- graph offsets from SORTED batch (no atomics) -----------
__global__ void goff_kernel(const void* __restrict__ batch) {
    int i = blockIdx.x * blockDim.x + threadIdx.x;
    if (i >= NN) return;
    int is64 = g_is64;
    int b = min(load_idx(batch, i, is64), GG - 1);
    int prev = (i == 0) ? -1 : min(load_idx(batch, i - 1, is64), GG - 1);
    for (int g = prev + 1; g <= b; g++) g_goff[g] = i;     // starts
    if (i == NN - 1)
        for (int g = b + 1; g <= GG; g++) g_goff[g] = NN;  // tail (incl. empty)
}

// ---------------- hierarchical exclusive scan of deg ----------------
__global__ void scan1_kernel() {          // block sums
    __shared__ int ws[8];
    int i = blockIdx.x * 256 + threadIdx.x;
    int lane = threadIdx.x & 31, w = threadIdx.x >> 5;
    int v = (i < NN) ? g_deg[i] : 0;
    int s = v;
    #pragma unroll
    for (int o = 16; o; o >>= 1) s += __shfl_xor_sync(0xffffffffu, s, o);
    if (lane == 0) ws[w] = s;
    __syncthreads();
    if (threadIdx.x == 0) {
        int tot = 0;
        #pragma unroll
        for (int k = 0; k < 8; k++) tot += ws[k];
        g_part[blockIdx.x] = tot;
    }
}

__global__ void scan2_kernel() {          // scan 391 partials (1 block)
    __shared__ int sm[512];
    int t = threadIdx.x;
    int v = (t < NB) ? g_part[t] : 0;
    sm[t] = v;
    __syncthreads();
    int acc = v;
    for (int d = 1; d < 512; d <<= 1) {
        int a = (t >= d) ? sm[t - d] : 0;
        __syncthreads();
        acc += a;
        sm[t] = acc;
        __syncthreads();
    }
    if (t < NB) g_part[t] = acc - v;      // exclusive block base
}

__global__ void scan3_kernel() {          // local exclusive scan + base
    __shared__ int wsum[8];
    int b = blockIdx.x, t = threadIdx.x;
    int i = b * 256 + t;
    int lane = t & 31, w = t >> 5;
    int v = (i < NN) ? g_deg[i] : 0;
    int sc = v;
    #pragma unroll
    for (int o = 1; o < 32; o <<= 1) {
        int u = __shfl_up_sync(0xffffffffu, sc, o);
        if (lane >= o) sc += u;
    }
    if (lane == 31) wsum[w] = sc;
    __syncthreads();
    if (t < 8) {
        int x = wsum[t];
        #pragma unroll
        for (int o = 1; o < 8; o <<= 1) {
            int u = __shfl_up_sync(0xffu, x, o);
            if (t >= o) x += u;
        }
        wsum[t] = x;
    }
    __syncthreads();
    int excl = sc - v + (w > 0 ? wsum[w - 1] : 0) + g_part[b];
    if (i < NN) { g_off[i] = excl; g_cursor[i] = excl; }
}

// ---------------- scatter edges (and self loops) into CSR ----------------
__global__ void scatter_kernel(const void* __restrict__ ei) {
    int idx = blockIdx.x * blockDim.x + threadIdx.x;
    if (idx >= EE + NN) return;
    int j, d;
    if (idx < EE) {
        int is64 = g_is64;
        j = load_idx(ei, idx, is64);
        d = load_idx(ei, (long long)EE + idx, is64);
    } else {
        j = d = idx - EE;
    }
    int pos = atomicAdd(&g_cursor[d], 1);
    g_csr[pos] = j;
}

// ---------------- GEMM: xw = x @ W, fused att epilogue ----------------
// 64-node x 64-col tile, K=128 in two 64-chunks. W staged transposed for
// conflict-free LDS.64 streams. Epilogue: bf16 store of xw + per-node/head
// attention dots computed from fp32 accumulators staged in smem.
#define KC 64
#define XS_STRIDE 66
__global__ void __launch_bounds__(256, 4) gemm_kernel(const float* __restrict__ x,
                                                      const float* __restrict__ W,
                                                      const float* __restrict__ att_src,
                                                      const float* __restrict__ att_dst) {
    __shared__ float xs [64][XS_STRIDE];
    __shared__ float wst[64][XS_STRIDE];
    int t = threadIdx.x;
    int n0 = blockIdx.x * 64;
    int tx = t & 15, ty = t >> 4;

    float acc[4][4] = {};

    for (int kc = 0; kc < 2; kc++) {
        int k0 = kc * KC;
        for (int idx = t; idx < 64 * 16; idx += 256) {
            int r = idx >> 4, q = idx & 15;
            int gn = n0 + r;
            float4 v = (gn < NN)
                ? *reinterpret_cast<const float4*>(&x[gn * DIMM + k0 + q * 4])
                : make_float4(0.f, 0.f, 0.f, 0.f);
            xs[r][q * 4 + 0] = v.x; xs[r][q * 4 + 1] = v.y;
            xs[r][q * 4 + 2] = v.z; xs[r][q * 4 + 3] = v.w;
        }
        for (int idx = t; idx < 64 * 64; idx += 256) {
            int k = idx >> 6, c = idx & 63;
            wst[c][k] = (c < HC) ? W[(k0 + k) * HC + c] : 0.f;
        }
        __syncthreads();

        #pragma unroll 4
        for (int k = 0; k < KC; k += 2) {
            float2 xv[4], wv[4];
            #pragma unroll
            for (int m = 0; m < 4; m++)
                xv[m] = *reinterpret_cast<const float2*>(&xs[ty + 16 * m][k]);
            #pragma unroll
            for (int n = 0; n < 4; n++)
                wv[n] = *reinterpret_cast<const float2*>(&wst[tx + 16 * n][k]);
            #pragma unroll
            for (int m = 0; m < 4; m++)
                #pragma unroll
                for (int n = 0; n < 4; n++) {
                    acc[m][n] += xv[m].x * wv[n].x;
                    acc[m][n] += xv[m].y * wv[n].y;
                }
        }
        __syncthreads();
    }

    // stage fp32 results into smem (reuse xs) + store bf16 messages
    float (*outs)[XS_STRIDE] = xs;
    #pragma unroll
    for (int m = 0; m < 4; m++) {
        int r = ty + 16 * m;
        int gn = n0 + r;
        #pragma unroll
        for (int n = 0; n < 4; n++) {
            int c = tx + 16 * n;
            if (c < HC) {
                outs[r][c] = acc[m][n];
                if (gn < NN) g_xwh[gn * HC + c] = __float2bfloat16(acc[m][n]);
            }
        }
    }
    __syncthreads();

    // attention dots: 64 nodes x 5 heads = 320 tasks
    for (int task = t; task < 64 * HH; task += 256) {
        int n = task / HH, h = task - n * HH;
        int gn = n0 + n;
        if (gn >= NN) continue;
        float s = 0.f, d = 0.f;
        #pragma unroll
        for (int c = 0; c < CC; c++) {
            float v = outs[n][h * CC + c];
            s += v * __ldg(&att_src[h * CC + c]);
            d += v * __ldg(&att_dst[h * CC + c]);
        }
        g_asrc8[gn * 8 + h] = s;
        g_adst8[gn * 8 + h] = d;
    }
}

// ---------------- aggregation: warp/node, 2-phase per 32-edge chunk -------
// Phase A (edge-parallel): lane e gathers asrc row (1 aligned 32B sector),
// computes 5 exp-logits, stages [j, ex0..4] to smem, accumulates denom.
// Phase B (channel-parallel): lanes<25 accumulate bf16 xw[j] * ex.
// Softmax max-subtraction dropped: logits O(1), softmax shift-invariant.
#define EST 6
__global__ void __launch_bounds__(256) aggregate_kernel(const float* __restrict__ bias) {
    __shared__ float esh[8][32 * EST];

    int w    = threadIdx.x >> 5;
    int lane = threadIdx.x & 31;
    int gw   = blockIdx.x * 8 + w;

    int base = g_off[gw];
    int deg  = g_deg[gw];

    float ad[HH];
    #pragma unroll
    for (int h = 0; h < HH; h++) ad[h] = g_adst8[gw * 8 + h];

    int   hsel = lane / 5;                 // head for this lane's channel pair
    float dacc[HH] = {};
    float2 acc = make_float2(0.f, 0.f);

    for (int c0 = 0; c0 < deg; c0 += 32) {
        int m = min(32, deg - c0);
        // ---- phase A ----
        float* rec = &esh[w][lane * EST];
        if (lane < m) {
            int j = g_csr[base + c0 + lane];
            rec[0] = __int_as_float(j);
            float4 a4 = *reinterpret_cast<const float4*>(&g_asrc8[j * 8]);
            float  a5 = g_asrc8[j * 8 + 4];
            float av[HH] = {a4.x, a4.y, a4.z, a4.w, a5};
            #pragma unroll
            for (int h = 0; h < HH; h++) {
                float tt = av[h] + ad[h];
                tt = (tt > 0.f) ? tt : NEG_SLOPE * tt;
                float e = __expf(tt);
                rec[1 + h] = e;
                dacc[h] += e;
            }
        }
        __syncwarp();
        // ---- phase B ----
        if (lane < 25) {
            const __nv_bfloat162* xwp =
                reinterpret_cast<const __nv_bfloat162*>(g_xwh) + lane;
            #pragma unroll 8
            for (int e = 0; e < m; e++) {
                const float* r = &esh[w][e * EST];
                int   je  = __float_as_int(r[0]);
                float exh = r[1 + hsel];
                float2 v = __bfloat1622float2(xwp[je * 25]);
                acc.x += exh * v.x;
                acc.y += exh * v.y;
            }
        }
        __syncwarp();
    }

    // reduce denominators across lanes
    #pragma unroll
    for (int h = 0; h < HH; h++) {
        #pragma unroll
        for (int o = 16; o; o >>= 1)
            dacc[h] += __shfl_xor_sync(0xffffffffu, dacc[h], o);
    }
    float dh = dacc[0];
    #pragma unroll
    for (int h = 1; h < HH; h++) if (hsel == h) dh = dacc[h];

    if (lane < 25) {
        int c = lane * 2;
        float ox = acc.x / dh + bias[c];
        float oy = acc.y / dh + bias[c + 1];
        ox = (ox > 0.f) ? ox : expm1f(ox);       // ELU fused
        oy = (oy > 0.f) ? oy : expm1f(oy);
        *reinterpret_cast<float2*>(&g_gout[gw * HC + c]) = make_float2(ox, oy);
    }
}

// ---------------- pool (mean per graph) + linear + sigmoid ----------------
__global__ void pool_kernel(const float* __restrict__ lin_w,
                            const float* __restrict__ lin_b,
                            float* __restrict__ out) {
    __shared__ float red[5][HC];
    __shared__ float hsh[HC];
    int t = threadIdx.x, g = blockIdx.x;
    int start = g_goff[g], end = g_goff[g + 1];
    int cnt = end - start;

    if (t < 250) {
        int nd = t / HC, c = t % HC;
        float p = 0.f;
        for (int r = start + nd; r < end; r += 5) p += g_gout[r * HC + c];
        red[nd][c] = p;
    }
    __syncthreads();
    if (t < HC) {
        float s = red[0][t] + red[1][t] + red[2][t] + red[3][t] + red[4][t];
        float hv = s / fmaxf((float)cnt, 1.f);
        out[g * HC + t] = hv;
        hsh[t] = hv * lin_w[t];
    }
    __syncthreads();
    if (t == 0) {
        float s = lin_b[0];
        #pragma unroll
        for (int c = 0; c < HC; c++) s += hsh[c];
        out[GG * HC + g] = 1.f / (1.f + __expf(-s));
    }
}

// ---------------- launch: fork CSR build onto side stream ----------------
extern "C" void kernel_launch(void* const* d_in, const int* in_sizes, int n_in,
                              void* d_out, int out_size) {
    const float* x       = (const float*)d_in[0];
    const float* W       = (const float*)d_in[1];
    const float* att_src = (const float*)d_in[2];
    const float* att_dst = (const float*)d_in[3];
    const float* bias    = (const float*)d_in[4];
    const float* lin_w   = (const float*)d_in[5];
    const float* lin_b   = (const float*)d_in[6];
    const void*  ei      = d_in[7];
    const void*  batch   = d_in[8];
    float*       out     = (float*)d_out;

    static cudaStream_t s2 = nullptr;
    static cudaEvent_t evFork = nullptr, evJoin = nullptr;
    if (!s2) {
        cudaStreamCreateWithFlags(&s2, cudaStreamNonBlocking);
        cudaEventCreateWithFlags(&evFork, cudaEventDisableTiming);
        cudaEventCreateWithFlags(&evJoin, cudaEventDisableTiming);
    }

    // fork: CSR build on s2, GEMM on legacy stream, join before aggregate
    cudaEventRecord(evFork, 0);
    cudaStreamWaitEvent(s2, evFork, 0);

    detect_kernel <<<1, 64, 0, s2>>>((const int*)ei);
    init_kernel   <<<NB, 256, 0, s2>>>();
    hist_kernel   <<<(EE + 255) / 256, 256, 0, s2>>>(ei);
    goff_kernel   <<<NB, 256, 0, s2>>>(batch);
    scan1_kernel  <<<NB, 256, 0, s2>>>();
    scan2_kernel  <<<1, 512, 0, s2>>>();
    scan3_kernel  <<<NB, 256, 0, s2>>>();
    scatter_kernel<<<(EE + NN + 255) / 256, 256, 0, s2>>>(ei);
    cudaEventRecord(evJoin, s2);

    gemm_kernel   <<<(NN + 63) / 64, 256>>>(x, W, att_src, att_dst);

    cudaStreamWaitEvent(0, evJoin, 0);
    aggregate_kernel<<<NN / 8, 256>>>(bias);   // 1 warp per node
    pool_kernel   <<<GG, 256>>>(lin_w, lin_b, out);
}

// round 9
// speedup vs baseline: 2.4791x; 1.0960x over previous
#include <cuda_runtime.h>
#include <cuda_fp16.h>

#define NN   100000
#define EE   1600000
#define DIMM 128
#define HH   5
#define CC   10
#define HC   50
#define GG   256
#define NEG_SLOPE 0.2f
#define NB   391            // ceil(NN/256)

// ---------------- static scratch (no allocation allowed) ----------------
__device__ __half g_xwh [NN * HC];  // fp16 x@W (messages)         10 MB
__device__ float  g_asrc8[NN * 8];  // src attn, padded row of 8   3.2 MB
__device__ float  g_adst8[NN * 8];  // dst attn, padded row of 8   3.2 MB
__device__ __half g_gout [NN * HC]; // elu(node output), fp16      10 MB
__device__ int    g_deg   [NN];
__device__ int    g_off   [NN];
__device__ int    g_cursor[NN];
__device__ int    g_csr   [EE + NN];// src ids grouped by dst (incl. self-loops)
__device__ int    g_part  [512];    // scan partials
__device__ int    g_goff  [GG + 1];
__device__ int    g_is64;           // 1 if index buffers are int64, 0 if int32

// ---------------- dtype probe (warp-parallel) ----------------
__global__ void detect_kernel(const int* __restrict__ ei32) {
    int t = threadIdx.x;                    // 64 threads
    int nz = (ei32[2 * t + 1] != 0) ? 1 : 0;
    unsigned b0 = __ballot_sync(0xffffffffu, nz && t < 32);
    __shared__ int hi;
    if (t == 32) hi = 0;
    __syncthreads();
    if (t >= 32 && nz) atomicOr(&hi, 1);
    __syncthreads();
    if (t == 0) g_is64 = (b0 == 0u && hi == 0) ? 1 : 0;
}

__device__ __forceinline__ int load_idx(const void* p, long long i, int is64) {
    int v = is64 ? (int)((const long long*)p)[i] : ((const int*)p)[i];
    return min(max(v, 0), NN - 1);    // defensive clamp (dead when dtype right)
}

// ---------------- init: deg=1 (self loop) ----------------
__global__ void init_kernel() {
    int i = blockIdx.x * blockDim.x + threadIdx.x;
    if (i < NN) g_deg[i] = 1;
}

// ---------------- histogram of edge dst ----------------
__global__ void hist_kernel(const void* __restrict__ ei) {
    int e = blockIdx.x * blockDim.x + threadIdx.x;
    if (e >= EE) return;
    int d = load_idx(ei, (long long)EE + e, g_is64);
    atomicAdd(&g_deg[d], 1);
}

// ---------------- graph offsets from SORTED batch (no atomics) -----------
__global__ void goff_kernel(const void* __restrict__ batch) {
    int i = blockIdx.x * blockDim.x + threadIdx.x;
    if (i >= NN) return;
    int is64 = g_is64;
    int b = min(load_idx(batch, i, is64), GG - 1);
    int prev = (i == 0) ? -1 : min(load_idx(batch, i - 1, is64), GG - 1);
    for (int g = prev + 1; g <= b; g++) g_goff[g] = i;     // starts
    if (i == NN - 1)
        for (int g = b + 1; g <= GG; g++) g_goff[g] = NN;  // tail (incl. empty)
}

// ---------------- hierarchical exclusive scan of deg ----------------
__global__ void scan1_kernel() {          // block sums
    __shared__ int ws[8];
    int i = blockIdx.x * 256 + threadIdx.x;
    int lane = threadIdx.x & 31, w = threadIdx.x >> 5;
    int v = (i < NN) ? g_deg[i] : 0;
    int s = v;
    #pragma unroll
    for (int o = 16; o; o >>= 1) s += __shfl_xor_sync(0xffffffffu, s, o);
    if (lane == 0) ws[w] = s;
    __syncthreads();
    if (threadIdx.x == 0) {
        int tot = 0;
        #pragma unroll
        for (int k = 0; k < 8; k++) tot += ws[k];
        g_part[blockIdx.x] = tot;
    }
}

__global__ void scan2_kernel() {          // scan 391 partials (1 block)
    __shared__ int sm[512];
    int t = threadIdx.x;
    int v = (t < NB) ? g_part[t] : 0;
    sm[t] = v;
    __syncthreads();
    int acc = v;
    for (int d = 1; d < 512; d <<= 1) {
        int a = (t >= d) ? sm[t - d] : 0;
        __syncthreads();
        acc += a;
        sm[t] = acc;
        __syncthreads();
    }
    if (t < NB) g_part[t] = acc - v;      // exclusive block base
}

__global__ void scan3_kernel() {          // local exclusive scan + base
    __shared__ int wsum[8];
    int b = blockIdx.x, t = threadIdx.x;
    int i = b * 256 + t;
    int lane = t & 31, w = t >> 5;
    int v = (i < NN) ? g_deg[i] : 0;
    int sc = v;
    #pragma unroll
    for (int o = 1; o < 32; o <<= 1) {
        int u = __shfl_up_sync(0xffffffffu, sc, o);
        if (lane >= o) sc += u;
    }
    if (lane == 31) wsum[w] = sc;
    __syncthreads();
    if (t < 8) {
        int x = wsum[t];
        #pragma unroll
        for (int o = 1; o < 8; o <<= 1) {
            int u = __shfl_up_sync(0xffu, x, o);
            if (t >= o) x += u;
        }
        wsum[t] = x;
    }
    __syncthreads();
    int excl = sc - v + (w > 0 ? wsum[w - 1] : 0) + g_part[b];
    if (i < NN) { g_off[i] = excl; g_cursor[i] = excl; }
}

// ---------------- scatter edges (and self loops) into CSR ----------------
__global__ void scatter_kernel(const void* __restrict__ ei) {
    int idx = blockIdx.x * blockDim.x + threadIdx.x;
    if (idx >= EE + NN) return;
    int j, d;
    if (idx < EE) {
        int is64 = g_is64;
        j = load_idx(ei, idx, is64);
        d = load_idx(ei, (long long)EE + idx, is64);
    } else {
        j = d = idx - EE;
    }
    int pos = atomicAdd(&g_cursor[d], 1);
    g_csr[pos] = j;
}

// ---------------- GEMM: xw = x @ W, fused att epilogue ----------------
#define KC 64
#define XS_STRIDE 66
__global__ void __launch_bounds__(256, 4) gemm_kernel(const float* __restrict__ x,
                                                      const float* __restrict__ W,
                                                      const float* __restrict__ att_src,
                                                      const float* __restrict__ att_dst) {
    __shared__ float xs [64][XS_STRIDE];
    __shared__ float wst[64][XS_STRIDE];
    int t = threadIdx.x;
    int n0 = blockIdx.x * 64;
    int tx = t & 15, ty = t >> 4;

    float acc[4][4] = {};

    for (int kc = 0; kc < 2; kc++) {
        int k0 = kc * KC;
        for (int idx = t; idx < 64 * 16; idx += 256) {
            int r = idx >> 4, q = idx & 15;
            int gn = n0 + r;
            float4 v = (gn < NN)
                ? *reinterpret_cast<const float4*>(&x[gn * DIMM + k0 + q * 4])
                : make_float4(0.f, 0.f, 0.f, 0.f);
            xs[r][q * 4 + 0] = v.x; xs[r][q * 4 + 1] = v.y;
            xs[r][q * 4 + 2] = v.z; xs[r][q * 4 + 3] = v.w;
        }
        for (int idx = t; idx < 64 * 64; idx += 256) {
            int k = idx >> 6, c = idx & 63;
            wst[c][k] = (c < HC) ? W[(k0 + k) * HC + c] : 0.f;
        }
        __syncthreads();

        #pragma unroll 4
        for (int k = 0; k < KC; k += 2) {
            float2 xv[4], wv[4];
            #pragma unroll
            for (int m = 0; m < 4; m++)
                xv[m] = *reinterpret_cast<const float2*>(&xs[ty + 16 * m][k]);
            #pragma unroll
            for (int n = 0; n < 4; n++)
                wv[n] = *reinterpret_cast<const float2*>(&wst[tx + 16 * n][k]);
            #pragma unroll
            for (int m = 0; m < 4; m++)
                #pragma unroll
                for (int n = 0; n < 4; n++) {
                    acc[m][n] += xv[m].x * wv[n].x;
                    acc[m][n] += xv[m].y * wv[n].y;
                }
        }
        __syncthreads();
    }

    // stage fp32 results into smem (reuse xs) + store fp16 messages
    float (*outs)[XS_STRIDE] = xs;
    #pragma unroll
    for (int m = 0; m < 4; m++) {
        int r = ty + 16 * m;
        int gn = n0 + r;
        #pragma unroll
        for (int n = 0; n < 4; n++) {
            int c = tx + 16 * n;
            if (c < HC) {
                outs[r][c] = acc[m][n];
                if (gn < NN) g_xwh[gn * HC + c] = __float2half_rn(acc[m][n]);
            }
        }
    }
    __syncthreads();

    // attention dots: 64 nodes x 5 heads = 320 tasks (fp32 accumulators)
    for (int task = t; task < 64 * HH; task += 256) {
        int n = task / HH, h = task - n * HH;
        int gn = n0 + n;
        if (gn >= NN) continue;
        float s = 0.f, d = 0.f;
        #pragma unroll
        for (int c = 0; c < CC; c++) {
            float v = outs[n][h * CC + c];
            s += v * __ldg(&att_src[h * CC + c]);
            d += v * __ldg(&att_dst[h * CC + c]);
        }
        g_asrc8[gn * 8 + h] = s;
        g_adst8[gn * 8 + h] = d;
    }
}

// ---------------- aggregation: warp/node, 2-phase per 32-edge chunk -------
// Phase A (edge-parallel): lane e gathers asrc row (aligned 32B), computes 5
// exp-logits, stages [j, ex0..4] to smem.
// Phase B (channel-parallel): lanes<25 accumulate fp16 xw[j]*ex AND their
// head's denominator (dsum += exh covers all edges -> no reduction needed).
// Softmax max-subtraction dropped: logits O(1), softmax shift-invariant.
#define EST 6
__global__ void __launch_bounds__(256) aggregate_kernel(const float* __restrict__ bias) {
    __shared__ float esh[8][32 * EST];

    int w    = threadIdx.x >> 5;
    int lane = threadIdx.x & 31;
    int gw   = blockIdx.x * 8 + w;

    int base = g_off[gw];
    int deg  = g_deg[gw];

    float ad[HH];
    #pragma unroll
    for (int h = 0; h < HH; h++) ad[h] = g_adst8[gw * 8 + h];

    int   hsel = lane / 5;                 // head for this lane's channel pair
    float dsum = 0.f;
    float2 acc = make_float2(0.f, 0.f);

    for (int c0 = 0; c0 < deg; c0 += 32) {
        int m = min(32, deg - c0);
        // ---- phase A ----
        float* rec = &esh[w][lane * EST];
        if (lane < m) {
            int j = g_csr[base + c0 + lane];
            rec[0] = __int_as_float(j);
            float4 a4 = *reinterpret_cast<const float4*>(&g_asrc8[j * 8]);
            float  a5 = g_asrc8[j * 8 + 4];
            float av[HH] = {a4.x, a4.y, a4.z, a4.w, a5};
            #pragma unroll
            for (int h = 0; h < HH; h++) {
                float tt = av[h] + ad[h];
                tt = (tt > 0.f) ? tt : NEG_SLOPE * tt;
                rec[1 + h] = __expf(tt);
            }
        }
        __syncwarp();
        // ---- phase B ----
        if (lane < 25) {
            const __half2* xwp = reinterpret_cast<const __half2*>(g_xwh) + lane;
            #pragma unroll 8
            for (int e = 0; e < m; e++) {
                const float* r = &esh[w][e * EST];
                int   je  = __float_as_int(r[0]);
                float exh = r[1 + hsel];
                float2 v = __half22float2(xwp[je * 25]);
                acc.x += exh * v.x;
                acc.y += exh * v.y;
                dsum  += exh;
            }
        }
        __syncwarp();
    }

    if (lane < 25) {
        int c = lane * 2;
        float ox = acc.x / dsum + bias[c];
        float oy = acc.y / dsum + bias[c + 1];
        ox = (ox > 0.f) ? ox : expm1f(ox);       // ELU fused
        oy = (oy > 0.f) ? oy : expm1f(oy);
        *reinterpret_cast<__half2*>(&g_gout[gw * HC + c]) =
            __floats2half2_rn(ox, oy);
    }
}

// ---------------- pool (mean per graph) + linear + sigmoid ----------------
__global__ void pool_kernel(const float* __restrict__ lin_w,
                            const float* __restrict__ lin_b,
                            float* __restrict__ out) {
    __shared__ float red[5][HC];
    __shared__ float hsh[HC];
    int t = threadIdx.x, g = blockIdx.x;
    int start = g_goff[g], end = g_goff[g + 1];
    int cnt = end - start;

    if (t < 250) {
        int nd = t / HC, c = t % HC;
        float p = 0.f;
        for (int r = start + nd; r < end; r += 5)
            p += __half2float(g_gout[r * HC + c]);
        red[nd][c] = p;
    }
    __syncthreads();
    if (t < HC) {
        float s = red[0][t] + red[1][t] + red[2][t] + red[3][t] + red[4][t];
        float hv = s / fmaxf((float)cnt, 1.f);
        out[g * HC + t] = hv;
        hsh[t] = hv * lin_w[t];
    }
    __syncthreads();
    if (t == 0) {
        float s = lin_b[0];
        #pragma unroll
        for (int c = 0; c < HC; c++) s += hsh[c];
        out[GG * HC + g] = 1.f / (1.f + __expf(-s));
    }
}

// ---------------- launch: fork CSR build onto side stream ----------------
extern "C" void kernel_launch(void* const* d_in, const int* in_sizes, int n_in,
                              void* d_out, int out_size) {
    const float* x       = (const float*)d_in[0];
    const float* W       = (const float*)d_in[1];
    const float* att_src = (const float*)d_in[2];
    const float* att_dst = (const float*)d_in[3];
    const float* bias    = (const float*)d_in[4];
    const float* lin_w   = (const float*)d_in[5];
    const float* lin_b   = (const float*)d_in[6];
    const void*  ei      = d_in[7];
    const void*  batch   = d_in[8];
    float*       out     = (float*)d_out;

    static cudaStream_t s2 = nullptr;
    static cudaEvent_t evFork = nullptr, evJoin = nullptr;
    if (!s2) {
        cudaStreamCreateWithFlags(&s2, cudaStreamNonBlocking);
        cudaEventCreateWithFlags(&evFork, cudaEventDisableTiming);
        cudaEventCreateWithFlags(&evJoin, cudaEventDisableTiming);
    }

    // fork: CSR build on s2, GEMM on legacy stream, join before aggregate
    cudaEventRecord(evFork, 0);
    cudaStreamWaitEvent(s2, evFork, 0);

    detect_kernel <<<1, 64, 0, s2>>>((const int*)ei);
    init_kernel   <<<NB, 256, 0, s2>>>();
    hist_kernel   <<<(EE + 255) / 256, 256, 0, s2>>>(ei);
    goff_kernel   <<<NB, 256, 0, s2>>>(batch);
    scan1_kernel  <<<NB, 256, 0, s2>>>();
    scan2_kernel  <<<1, 512, 0, s2>>>();
    scan3_kernel  <<<NB, 256, 0, s2>>>();
    scatter_kernel<<<(EE + NN + 255) / 256, 256, 0, s2>>>(ei);
    cudaEventRecord(evJoin, s2);

    gemm_kernel   <<<(NN + 63) / 64, 256>>>(x, W, att_src, att_dst);

    cudaStreamWaitEvent(0, evJoin, 0);
    aggregate_kernel<<<NN / 8, 256>>>(bias);   // 1 warp per node
    pool_kernel   <<<GG, 256>>>(lin_w, lin_b, out);
}